// round 6
// baseline (speedup 1.0000x reference)
#include <cuda_runtime.h>
#include <cstdint>
#include <math.h>

// Problem constants (fixed by reference)
#define BB 256
#define PP 16
#define LL 4
#define EE 128
#define NPAIR 4096          // B*P
#define NNODE 512
#define C1 512
#define C2 256
#define LIST_CAP 64
#define XSTR 132            // padded stride (floats) for both ws and xs

typedef unsigned long long ull;

// ---------------- device scratch (no allocations allowed) ----------------
__device__ float g_bufA[NPAIR * 2 * EE];   // 4 MB ping
__device__ float g_bufB[NPAIR * 2 * EE];   // 4 MB pong
__device__ float g_pooledT[2 * EE * BB];   // [f][b]
__device__ float g_h1T[C1 * BB];           // [j][b]
__device__ float g_h2T[C2 * BB];           // [j][b]
__device__ int   g_cnt[LL * NNODE];
__device__ int   g_list[LL * NNODE * LIST_CAP];

// ---------------- f32x2 packed math ----------------
__device__ __forceinline__ void fma2(ull& d, ull a, ull b) {
    asm("fma.rn.f32x2 %0, %1, %2, %0;" : "+l"(d) : "l"(a), "l"(b));
}
__device__ __forceinline__ float hsum2(ull a) {
    return __uint_as_float((unsigned)a) + __uint_as_float((unsigned)(a >> 32));
}
__device__ __forceinline__ ull pack2(float x) {
    ull r; unsigned u = __float_as_uint(x);
    asm("mov.b64 %0, {%1, %2};" : "=l"(r) : "r"(u), "r"(u));
    return r;
}
__device__ __forceinline__ void cpasync16(uint32_t dst, const void* src) {
    asm volatile("cp.async.cg.shared.global [%0], [%1], 16;" :: "r"(dst), "l"(src));
}

// ---------------- list building: bucket pairs by (layer, node) ----------------
__global__ void build_lists_kernel(const int* __restrict__ mids)
{
    int idx = blockIdx.x * 256 + threadIdx.x;      // 0 .. NPAIR*LL-1
    if (idx >= NPAIR * LL) return;
    int p = idx >> 2, l = idx & 3;
    int node = mids[p * LL + l];
    int pos = atomicAdd(&g_cnt[l * NNODE + node], 1);
    if (pos < LIST_CAP)
        g_list[(l * NNODE + node) * LIST_CAP + pos] = p;
}

// ---------------- layer kernel: one block per node (all 128 rows) ----------------
// dyn smem: ws 128x132 floats (67584B) + xs 16x132 floats (8448B) = 76032B
#define SMEM_LAYER ((EE * XSTR + 16 * XSTR) * 4)

template <bool FIRST>
__global__ __launch_bounds__(256, 2) void layer_kernel(
    const float* __restrict__ Wg, const float* __restrict__ bias, int layer,
    const int* __restrict__ sids, const int* __restrict__ eids,
    const float* __restrict__ embed,
    const float* __restrict__ bufIn, float* __restrict__ bufOut)
{
    extern __shared__ float sm[];
    float* ws = sm;                    // 128 x 132
    float* xs = sm + EE * XSTR;        // 16 x 132
    __shared__ int slist[LIST_CAP];

    const int tid  = threadIdx.x;
    const int node = blockIdx.x;

    int kp = g_cnt[layer * NNODE + node];
    kp = kp < LIST_CAP ? kp : LIST_CAP;
    if (kp == 0) return;

    // Stage full W[node] (64KB) into padded shared via cp.async
    {
        uint32_t ws_u = (uint32_t)__cvta_generic_to_shared(ws);
        const float4* wsrc = (const float4*)(Wg + (size_t)node * (EE * EE));
        #pragma unroll
        for (int k = 0; k < 16; ++k) {
            int f = tid + k * 256;                 // 0..4095 float4s
            int r = f >> 5, i4 = f & 31;
            cpasync16(ws_u + (r * XSTR + i4 * 4) * 4, wsrc + f);
        }
        asm volatile("cp.async.commit_group;");
    }

    if (tid < LIST_CAP)
        slist[tid] = g_list[(layer * NNODE + node) * LIST_CAP + tid];

    // warp/lane decomposition
    const int lane = tid & 31, w = tid >> 5;
    const int rq = w & 3;              // row quarter (32 rows each)
    const int vg = w >> 2;             // vector group (8 vecs each)
    const int rowlane = lane >> 2;     // 0..7
    const int vl = lane & 3;           // 0..3

    int   rows[4];
    float bv[4];
    #pragma unroll
    for (int j = 0; j < 4; ++j) {
        rows[j] = rq * 32 + rowlane + 8 * j;
        bv[j] = bias[node * EE + rows[j]];
    }
    const int vbase = vg * 8 + vl;     // vectors vbase, vbase+4

    for (int c0 = 0; c0 < kp; c0 += 8) {
        const int nv = 2 * min(8, kp - c0);
        __syncthreads();   // prev chunk compute done; slist visible (1st iter)

        // stage xs: 16 vectors x 128 floats (2 float4 per thread), zero-padded
        #pragma unroll
        for (int k = 0; k < 2; ++k) {
            int f = tid + k * 256;                 // 0..511 float4s
            int v = f >> 5, i4 = f & 31;
            float4 val = make_float4(0.f, 0.f, 0.f, 0.f);
            if (v < nv) {
                int pr = slist[c0 + (v >> 1)];
                if (FIRST) {
                    int id = (v & 1) ? eids[pr] : sids[pr];
                    val = ((const float4*)embed)[(size_t)id * 32 + i4];
                } else {
                    val = ((const float4*)bufIn)[((size_t)pr * 2 + (v & 1)) * 32 + i4];
                }
            }
            *(float4*)&xs[v * XSTR + i4 * 4] = val;
        }
        if (c0 == 0) asm volatile("cp.async.wait_group 0;");
        __syncthreads();

        // compute: 4 rows x 2 vectors per lane
        ull acc[4][2];
        #pragma unroll
        for (int j = 0; j < 4; ++j) { acc[j][0] = 0ull; acc[j][1] = 0ull; }

        #pragma unroll 4
        for (int is = 0; is < 32; ++is) {
            ulonglong2 wv[4];
            #pragma unroll
            for (int j = 0; j < 4; ++j)
                wv[j] = *(ulonglong2*)&ws[rows[j] * XSTR + is * 4];
            ulonglong2 xv[2];
            #pragma unroll
            for (int m = 0; m < 2; ++m)
                xv[m] = *(ulonglong2*)&xs[(vbase + 4 * m) * XSTR + is * 4];
            #pragma unroll
            for (int j = 0; j < 4; ++j) {
                #pragma unroll
                for (int m = 0; m < 2; ++m) {
                    fma2(acc[j][m], wv[j].x, xv[m].x);
                    fma2(acc[j][m], wv[j].y, xv[m].y);
                }
            }
        }

        #pragma unroll
        for (int m = 0; m < 2; ++m) {
            int v = vbase + 4 * m;
            if (v < nv) {
                int pr = slist[c0 + (v >> 1)];
                float* dst = bufOut + ((size_t)pr * 2 + (v & 1)) * EE;
                #pragma unroll
                for (int j = 0; j < 4; ++j)
                    dst[rows[j]] = hsum2(acc[j][m]) + bv[j];
            }
        }
    }
}

// ---------------- pooling: pooledT[f][b] ----------------
__global__ void pool_kernel(const float* __restrict__ buf,
                            const int* __restrict__ counts,
                            float* __restrict__ pooledT)
{
    const int b = blockIdx.x;
    const int f = threadIdx.x;          // 0..255
    const int half = f >> 7, fi = f & 127;
    float acc = 0.f, cs = 0.f;
    #pragma unroll
    for (int p = 0; p < PP; ++p) {
        float c = (float)counts[b * PP + p];
        acc += c * buf[((size_t)((b * PP + p) * 2 + half)) * EE + fi];
        cs += c;
    }
    pooledT[(size_t)f * BB + b] = acc / cs;
}

// ---------------- MLP layer (relu): yT[j][b] ----------------
template <int IN>
__global__ void mlp_kernel(const float* __restrict__ Wm, const float* __restrict__ bm,
                           const float* __restrict__ xT, float* __restrict__ yT)
{
    __shared__ float wt[IN * 8];
    const int jt = blockIdx.x * 8;
    const int t = threadIdx.x;          // batch index
    for (int f = t; f < IN * 8; f += 256) {
        int jj = f / IN, i = f % IN;
        wt[i * 8 + jj] = Wm[(size_t)(jt + jj) * IN + i];
    }
    __syncthreads();

    ull acc[4] = {0ull, 0ull, 0ull, 0ull};
    #pragma unroll 8
    for (int i = 0; i < IN; ++i) {
        ull pp = pack2(xT[(size_t)i * BB + t]);
        ulonglong2 wa = *(ulonglong2*)&wt[i * 8];
        ulonglong2 wb = *(ulonglong2*)&wt[i * 8 + 4];
        fma2(acc[0], wa.x, pp);
        fma2(acc[1], wa.y, pp);
        fma2(acc[2], wb.x, pp);
        fma2(acc[3], wb.y, pp);
    }
    #pragma unroll
    for (int q = 0; q < 4; ++q) {
        int j0 = jt + 2 * q, j1 = j0 + 1;
        float v0 = __uint_as_float((unsigned)acc[q]) + bm[j0];
        float v1 = __uint_as_float((unsigned)(acc[q] >> 32)) + bm[j1];
        yT[(size_t)j0 * BB + t] = fmaxf(v0, 0.f);
        yT[(size_t)j1 * BB + t] = fmaxf(v1, 0.f);
    }
}

// ---------------- final ----------------
__global__ void out_kernel(const float* __restrict__ W3, const float* __restrict__ b3,
                           const float* __restrict__ h2T, float* __restrict__ out)
{
    const int t = threadIdx.x;
    float acc = 0.f;
    #pragma unroll 8
    for (int j = 0; j < C2; ++j)
        acc += W3[j] * h2T[(size_t)j * BB + t];
    acc += b3[0];
    out[t] = 1.f / (1.f + expf(-acc));
}

// ---------------- launch ----------------
extern "C" void kernel_launch(void* const* d_in, const int* in_sizes, int n_in,
                              void* d_out, int out_size)
{
    const int*   sids   = (const int*)d_in[0];
    const int*   eids   = (const int*)d_in[1];
    const int*   mids   = (const int*)d_in[2];
    const int*   counts = (const int*)d_in[3];
    const float* embed  = (const float*)d_in[4];
    const float* W      = (const float*)d_in[5];
    const float* bnode  = (const float*)d_in[6];
    const float* W1     = (const float*)d_in[7];
    const float* b1     = (const float*)d_in[8];
    const float* W2     = (const float*)d_in[9];
    const float* b2     = (const float*)d_in[10];
    const float* W3     = (const float*)d_in[11];
    const float* b3     = (const float*)d_in[12];

    float *bufA, *bufB, *pooledT, *h1T, *h2T;
    int *cnt;
    cudaGetSymbolAddress((void**)&bufA, g_bufA);
    cudaGetSymbolAddress((void**)&bufB, g_bufB);
    cudaGetSymbolAddress((void**)&pooledT, g_pooledT);
    cudaGetSymbolAddress((void**)&h1T, g_h1T);
    cudaGetSymbolAddress((void**)&h2T, g_h2T);
    cudaGetSymbolAddress((void**)&cnt, g_cnt);

    const int smem = SMEM_LAYER;   // 76032 bytes
    cudaFuncSetAttribute(layer_kernel<true>,  cudaFuncAttributeMaxDynamicSharedMemorySize, smem);
    cudaFuncSetAttribute(layer_kernel<false>, cudaFuncAttributeMaxDynamicSharedMemorySize, smem);

    // reset counters + build node->pair lists for all 4 layers
    cudaMemsetAsync(cnt, 0, LL * NNODE * sizeof(int));
    build_lists_kernel<<<(NPAIR * LL + 255) / 256, 256>>>(mids);

    layer_kernel<true ><<<NNODE, 256, smem>>>(W, bnode, 0, sids, eids, embed, nullptr, bufA);
    layer_kernel<false><<<NNODE, 256, smem>>>(W, bnode, 1, sids, eids, embed, bufA, bufB);
    layer_kernel<false><<<NNODE, 256, smem>>>(W, bnode, 2, sids, eids, embed, bufB, bufA);
    layer_kernel<false><<<NNODE, 256, smem>>>(W, bnode, 3, sids, eids, embed, bufA, bufB);

    pool_kernel<<<BB, 256>>>(bufB, counts, pooledT);
    mlp_kernel<2 * EE><<<C1 / 8, 256>>>(W1, b1, pooledT, h1T);
    mlp_kernel<C1>    <<<C2 / 8, 256>>>(W2, b2, h1T, h2T);
    out_kernel<<<1, 256>>>(W3, b3, h2T, (float*)d_out);
}

// round 7
// speedup vs baseline: 1.0841x; 1.0841x over previous
#include <cuda_runtime.h>
#include <cstdint>
#include <math.h>

// Problem constants (fixed by reference)
#define BB 256
#define PP 16
#define LL 4
#define EE 128
#define NPAIR 4096          // B*P
#define NNODE 512
#define C1 512
#define C2 256
#define LIST_CAP 64
#define XSTR 132            // padded stride (floats) for ws and xs
#define ITEMS_MAX 1024      // >= 512 + 4096/8 (proven bound 960)

typedef unsigned long long ull;

// ---------------- device scratch (no allocations allowed) ----------------
__device__ float g_bufA[NPAIR * 2 * EE];   // 4 MB ping
__device__ float g_bufB[NPAIR * 2 * EE];   // 4 MB pong
__device__ float g_pooledT[2 * EE * BB];   // [f][b]
__device__ float g_h1T[C1 * BB];           // [j][b]
__device__ float g_h2T[C2 * BB];           // [j][b]
__device__ int   g_meta[LL * NNODE + LL];  // per-(layer,node) counts, then per-layer item counts
__device__ int   g_list[LL * NNODE * LIST_CAP];
__device__ int   g_items[LL * ITEMS_MAX];  // packed (node<<6)|c0

// ---------------- f32x2 packed math ----------------
__device__ __forceinline__ void fma2(ull& d, ull a, ull b) {
    asm("fma.rn.f32x2 %0, %1, %2, %0;" : "+l"(d) : "l"(a), "l"(b));
}
__device__ __forceinline__ float hsum2(ull a) {
    return __uint_as_float((unsigned)a) + __uint_as_float((unsigned)(a >> 32));
}
__device__ __forceinline__ ull pack2(float x) {
    ull r; unsigned u = __float_as_uint(x);
    asm("mov.b64 %0, {%1, %2};" : "=l"(r) : "r"(u), "r"(u));
    return r;
}
__device__ __forceinline__ void cpasync16(uint32_t dst, const void* src) {
    asm volatile("cp.async.cg.shared.global [%0], [%1], 16;" :: "r"(dst), "l"(src));
}

// ---------------- list building: bucket pairs by (layer, node) ----------------
__global__ void build_lists_kernel(const int* __restrict__ mids)
{
    int idx = blockIdx.x * 256 + threadIdx.x;      // 0 .. NPAIR*LL-1
    if (idx >= NPAIR * LL) return;
    int p = idx >> 2, l = idx & 3;
    int node = mids[p * LL + l];
    int pos = atomicAdd(&g_meta[l * NNODE + node], 1);
    if (pos < LIST_CAP)
        g_list[(l * NNODE + node) * LIST_CAP + pos] = p;
}

// ---------------- item building: one item per (layer, node, 8-pair chunk) ----------------
__global__ void build_items_kernel()
{
    int idx = blockIdx.x * 256 + threadIdx.x;      // 0 .. LL*NNODE-1
    if (idx >= LL * NNODE) return;
    int l = idx >> 9, node = idx & (NNODE - 1);
    int c = g_meta[idx];
    c = c < LIST_CAP ? c : LIST_CAP;
    int nch = (c + 7) >> 3;
    if (nch > 0) {
        int base = atomicAdd(&g_meta[LL * NNODE + l], nch);
        for (int i = 0; i < nch; ++i)
            g_items[l * ITEMS_MAX + base + i] = (node << 6) | (i * 8);
    }
}

// ---------------- layer kernel: one block per (node, chunk) item ----------------
// dyn smem: ws 128x132 (67584B) + xs 16x132 (8448B) = 76032B  -> 3 blocks/SM
#define SMEM_LAYER ((EE * XSTR + 16 * XSTR) * 4)

template <bool FIRST>
__global__ __launch_bounds__(256, 3) void layer_kernel(
    const float* __restrict__ Wg, const float* __restrict__ bias, int layer,
    const int* __restrict__ sids, const int* __restrict__ eids,
    const float* __restrict__ embed,
    const float* __restrict__ bufIn, float* __restrict__ bufOut)
{
    const int nitems = g_meta[LL * NNODE + layer];
    if ((int)blockIdx.x >= nitems) return;

    extern __shared__ float sm[];
    float* ws = sm;                    // 128 x 132
    float* xs = sm + EE * XSTR;        // 16 x 132

    const int item = g_items[layer * ITEMS_MAX + blockIdx.x];
    const int node = item >> 6;
    const int c0   = item & 63;
    int kp = g_meta[layer * NNODE + node];
    kp = kp < LIST_CAP ? kp : LIST_CAP;
    const int nv = 2 * min(8, kp - c0);
    const int* lst = &g_list[(layer * NNODE + node) * LIST_CAP + c0];

    const int tid = threadIdx.x;
    const int lane = tid & 31, w = tid >> 5;

    // ---- W stage: each warp loads ONLY its own 16 rows (self-contained pipelining) ----
    {
        uint32_t ws_u = (uint32_t)__cvta_generic_to_shared(ws);
        const float4* wsrc = (const float4*)(Wg + (size_t)node * (EE * EE));
        #pragma unroll
        for (int k = 0; k < 16; ++k) {
            int f = w * 512 + k * 32 + lane;       // row = w*16+k, col4 = lane
            cpasync16(ws_u + ((w * 16 + k) * XSTR + lane * 4) * 4, wsrc + f);
        }
        asm volatile("cp.async.commit_group;");
    }

    // ---- xs gather: 16 vectors x 128 floats (2 float4/thread), zero-padded ----
    #pragma unroll
    for (int k = 0; k < 2; ++k) {
        int f = tid + k * 256;                     // 0..511 float4s
        int v = f >> 5, i4 = f & 31;
        float4 val = make_float4(0.f, 0.f, 0.f, 0.f);
        if (v < nv) {
            int pr = lst[v >> 1];
            if (FIRST) {
                int id = (v & 1) ? eids[pr] : sids[pr];
                val = ((const float4*)embed)[(size_t)id * 32 + i4];
            } else {
                val = ((const float4*)bufIn)[((size_t)pr * 2 + (v & 1)) * 32 + i4];
            }
        }
        *(float4*)&xs[v * XSTR + i4 * 4] = val;
    }
    __syncthreads();                               // xs visible to all warps

    // ---- wait for OWN warp's W rows only, then compute ----
    asm volatile("cp.async.wait_group 0;");
    __syncwarp();

    const int rowlane = lane >> 2;                 // 0..7
    const int vl = lane & 3;                       // 0..3
    const int r0 = w * 16 + rowlane;
    const int r1 = r0 + 8;
    const float bv0 = bias[node * EE + r0];
    const float bv1 = bias[node * EE + r1];

    ull acc[2][4];
    #pragma unroll
    for (int m = 0; m < 4; ++m) { acc[0][m] = 0ull; acc[1][m] = 0ull; }

    #pragma unroll 4
    for (int is = 0; is < 32; ++is) {
        ulonglong2 wv0 = *(ulonglong2*)&ws[r0 * XSTR + is * 4];
        ulonglong2 wv1 = *(ulonglong2*)&ws[r1 * XSTR + is * 4];
        #pragma unroll
        for (int m = 0; m < 4; ++m) {
            ulonglong2 xv = *(ulonglong2*)&xs[(vl + 4 * m) * XSTR + is * 4];
            fma2(acc[0][m], wv0.x, xv.x);
            fma2(acc[0][m], wv0.y, xv.y);
            fma2(acc[1][m], wv1.x, xv.x);
            fma2(acc[1][m], wv1.y, xv.y);
        }
    }

    #pragma unroll
    for (int m = 0; m < 4; ++m) {
        int v = vl + 4 * m;
        if (v < nv) {
            int pr = lst[v >> 1];
            float* dst = bufOut + ((size_t)pr * 2 + (v & 1)) * EE;
            dst[r0] = hsum2(acc[0][m]) + bv0;
            dst[r1] = hsum2(acc[1][m]) + bv1;
        }
    }
}

// ---------------- pooling: pooledT[f][b] ----------------
__global__ void pool_kernel(const float* __restrict__ buf,
                            const int* __restrict__ counts,
                            float* __restrict__ pooledT)
{
    const int b = blockIdx.x;
    const int f = threadIdx.x;          // 0..255
    const int half = f >> 7, fi = f & 127;
    float acc = 0.f, cs = 0.f;
    #pragma unroll
    for (int p = 0; p < PP; ++p) {
        float c = (float)counts[b * PP + p];
        acc += c * buf[((size_t)((b * PP + p) * 2 + half)) * EE + fi];
        cs += c;
    }
    pooledT[(size_t)f * BB + b] = acc / cs;
}

// ---------------- MLP layer (relu): yT[j][b] ----------------
template <int IN>
__global__ void mlp_kernel(const float* __restrict__ Wm, const float* __restrict__ bm,
                           const float* __restrict__ xT, float* __restrict__ yT)
{
    __shared__ float wt[IN * 8];
    const int jt = blockIdx.x * 8;
    const int t = threadIdx.x;          // batch index
    for (int f = t; f < IN * 8; f += 256) {
        int jj = f / IN, i = f % IN;
        wt[i * 8 + jj] = Wm[(size_t)(jt + jj) * IN + i];
    }
    __syncthreads();

    ull acc[4] = {0ull, 0ull, 0ull, 0ull};
    #pragma unroll 8
    for (int i = 0; i < IN; ++i) {
        ull pp = pack2(xT[(size_t)i * BB + t]);
        ulonglong2 wa = *(ulonglong2*)&wt[i * 8];
        ulonglong2 wb = *(ulonglong2*)&wt[i * 8 + 4];
        fma2(acc[0], wa.x, pp);
        fma2(acc[1], wa.y, pp);
        fma2(acc[2], wb.x, pp);
        fma2(acc[3], wb.y, pp);
    }
    #pragma unroll
    for (int q = 0; q < 4; ++q) {
        int j0 = jt + 2 * q, j1 = j0 + 1;
        float v0 = __uint_as_float((unsigned)acc[q]) + bm[j0];
        float v1 = __uint_as_float((unsigned)(acc[q] >> 32)) + bm[j1];
        yT[(size_t)j0 * BB + t] = fmaxf(v0, 0.f);
        yT[(size_t)j1 * BB + t] = fmaxf(v1, 0.f);
    }
}

// ---------------- final ----------------
__global__ void out_kernel(const float* __restrict__ W3, const float* __restrict__ b3,
                           const float* __restrict__ h2T, float* __restrict__ out)
{
    const int t = threadIdx.x;
    float acc = 0.f;
    #pragma unroll 8
    for (int j = 0; j < C2; ++j)
        acc += W3[j] * h2T[(size_t)j * BB + t];
    acc += b3[0];
    out[t] = 1.f / (1.f + expf(-acc));
}

// ---------------- launch ----------------
extern "C" void kernel_launch(void* const* d_in, const int* in_sizes, int n_in,
                              void* d_out, int out_size)
{
    const int*   sids   = (const int*)d_in[0];
    const int*   eids   = (const int*)d_in[1];
    const int*   mids   = (const int*)d_in[2];
    const int*   counts = (const int*)d_in[3];
    const float* embed  = (const float*)d_in[4];
    const float* W      = (const float*)d_in[5];
    const float* bnode  = (const float*)d_in[6];
    const float* W1     = (const float*)d_in[7];
    const float* b1     = (const float*)d_in[8];
    const float* W2     = (const float*)d_in[9];
    const float* b2     = (const float*)d_in[10];
    const float* W3     = (const float*)d_in[11];
    const float* b3     = (const float*)d_in[12];

    float *bufA, *bufB, *pooledT, *h1T, *h2T;
    int *meta;
    cudaGetSymbolAddress((void**)&bufA, g_bufA);
    cudaGetSymbolAddress((void**)&bufB, g_bufB);
    cudaGetSymbolAddress((void**)&pooledT, g_pooledT);
    cudaGetSymbolAddress((void**)&h1T, g_h1T);
    cudaGetSymbolAddress((void**)&h2T, g_h2T);
    cudaGetSymbolAddress((void**)&meta, g_meta);

    const int smem = SMEM_LAYER;   // 76032 bytes
    cudaFuncSetAttribute(layer_kernel<true>,  cudaFuncAttributeMaxDynamicSharedMemorySize, smem);
    cudaFuncSetAttribute(layer_kernel<false>, cudaFuncAttributeMaxDynamicSharedMemorySize, smem);

    // reset counters + build node->pair lists + work items for all 4 layers
    cudaMemsetAsync(meta, 0, (LL * NNODE + LL) * sizeof(int));
    build_lists_kernel<<<(NPAIR * LL + 255) / 256, 256>>>(mids);
    build_items_kernel<<<(LL * NNODE + 255) / 256, 256>>>();

    layer_kernel<true ><<<ITEMS_MAX, 256, smem>>>(W, bnode, 0, sids, eids, embed, nullptr, bufA);
    layer_kernel<false><<<ITEMS_MAX, 256, smem>>>(W, bnode, 1, sids, eids, embed, bufA, bufB);
    layer_kernel<false><<<ITEMS_MAX, 256, smem>>>(W, bnode, 2, sids, eids, embed, bufB, bufA);
    layer_kernel<false><<<ITEMS_MAX, 256, smem>>>(W, bnode, 3, sids, eids, embed, bufA, bufB);

    pool_kernel<<<BB, 256>>>(bufB, counts, pooledT);
    mlp_kernel<2 * EE><<<C1 / 8, 256>>>(W1, b1, pooledT, h1T);
    mlp_kernel<C1>    <<<C2 / 8, 256>>>(W2, b2, h1T, h2T);
    out_kernel<<<1, 256>>>(W3, b3, h2T, (float*)d_out);
}

// round 8
// speedup vs baseline: 1.1337x; 1.0458x over previous
#include <cuda_runtime.h>
#include <cstdint>
#include <math.h>

// Problem constants (fixed by reference)
#define BB 256
#define PP 16
#define LL 4
#define EE 128
#define NPAIR 4096          // B*P
#define NNODE 512
#define C1 512
#define C2 256
#define LIST_CAP 64
#define XSTR 132            // padded stride (floats) for ws and xs
#define ITEMS_MAX 768       // >= sum ceil(k/16) (proven bound 768)

typedef unsigned long long ull;

// ---------------- device scratch (no allocations allowed) ----------------
__device__ float g_bufA[NPAIR * 2 * EE];   // 4 MB ping
__device__ float g_bufB[NPAIR * 2 * EE];   // 4 MB pong
__device__ float g_pooledT[2 * EE * BB];   // [f][b]
__device__ float g_h1T[C1 * BB];           // [j][b]
__device__ float g_h2T[C2 * BB];           // [j][b]
__device__ int   g_meta[LL * NNODE + LL];  // per-(layer,node) counts, then per-layer item counts
__device__ int   g_list[LL * NNODE * LIST_CAP];
__device__ int   g_items[LL * ITEMS_MAX];  // packed (node<<6)|c0

// ---------------- f32x2 packed math ----------------
__device__ __forceinline__ void fma2(ull& d, ull a, ull b) {
    asm("fma.rn.f32x2 %0, %1, %2, %0;" : "+l"(d) : "l"(a), "l"(b));
}
__device__ __forceinline__ float hsum2(ull a) {
    return __uint_as_float((unsigned)a) + __uint_as_float((unsigned)(a >> 32));
}
__device__ __forceinline__ ull pack2(float x) {
    ull r; unsigned u = __float_as_uint(x);
    asm("mov.b64 %0, {%1, %2};" : "=l"(r) : "r"(u), "r"(u));
    return r;
}
__device__ __forceinline__ void cpasync16(uint32_t dst, const void* src) {
    asm volatile("cp.async.cg.shared.global [%0], [%1], 16;" :: "r"(dst), "l"(src));
}

// ---------------- list building: bucket pairs by (layer, node) ----------------
__global__ void build_lists_kernel(const int* __restrict__ mids)
{
    int idx = blockIdx.x * 256 + threadIdx.x;      // 0 .. NPAIR*LL-1
    if (idx >= NPAIR * LL) return;
    int p = idx >> 2, l = idx & 3;
    int node = mids[p * LL + l];
    int pos = atomicAdd(&g_meta[l * NNODE + node], 1);
    if (pos < LIST_CAP)
        g_list[(l * NNODE + node) * LIST_CAP + pos] = p;
}

// ---------------- item building: one item per (layer, node, 16-pair chunk) ----------------
__global__ void build_items_kernel()
{
    int idx = blockIdx.x * 256 + threadIdx.x;      // 0 .. LL*NNODE-1
    if (idx >= LL * NNODE) return;
    int l = idx >> 9, node = idx & (NNODE - 1);
    int c = g_meta[idx];
    c = c < LIST_CAP ? c : LIST_CAP;
    int nch = (c + 15) >> 4;
    if (nch > 0) {
        int base = atomicAdd(&g_meta[LL * NNODE + l], nch);
        for (int i = 0; i < nch; ++i)
            g_items[l * ITEMS_MAX + base + i] = (node << 6) | (i * 16);
    }
}

// ---------------- compute tile, M active vector-groups (compile-time) ----------------
// lane tile: 4 rows x (M x 1) vectors; W loads shared across groups
template <int M>
__device__ __forceinline__ void compute_tile(
    const float* ws, const float* xs, const int* lst,
    float* bufOut, const float* bias_g,
    int w, int rowlane, int vl, int rh, int nv)
{
    const int rl0 = w * 16 + rowlane;      // local rows rl0 + {0,4,8,12}
    ull acc[M][4];
    #pragma unroll
    for (int m = 0; m < M; ++m)
        #pragma unroll
        for (int j = 0; j < 4; ++j) acc[m][j] = 0ull;

    #pragma unroll 4
    for (int is = 0; is < 32; ++is) {
        ulonglong2 wv[4];
        #pragma unroll
        for (int j = 0; j < 4; ++j)
            wv[j] = *(ulonglong2*)&ws[(rl0 + 4 * j) * XSTR + is * 4];
        #pragma unroll
        for (int m = 0; m < M; ++m) {
            ulonglong2 xv = *(ulonglong2*)&xs[(m * 8 + vl) * XSTR + is * 4];
            #pragma unroll
            for (int j = 0; j < 4; ++j) {
                fma2(acc[m][j], wv[j].x, xv.x);
                fma2(acc[m][j], wv[j].y, xv.y);
            }
        }
    }

    #pragma unroll
    for (int m = 0; m < M; ++m) {
        int v = m * 8 + vl;
        if (v < nv) {
            int pr = lst[v >> 1];
            float* dst = bufOut + ((size_t)pr * 2 + (v & 1)) * EE + rh * 64;
            #pragma unroll
            for (int j = 0; j < 4; ++j)
                dst[rl0 + 4 * j] = hsum2(acc[m][j]) + bias_g[rl0 + 4 * j];
        }
    }
}

// ---------------- layer kernel: block = (node-chunk item) x (row half) ----------------
// dyn smem: ws 64x132 (33792B) + xs 32x132 (16896B) = 50688B -> 4 blocks/SM
#define SMEM_LAYER ((64 * XSTR + 32 * XSTR) * 4)

template <bool FIRST>
__global__ __launch_bounds__(128, 4) void layer_kernel(
    const float* __restrict__ Wg, const float* __restrict__ bias, int layer,
    const int* __restrict__ sids, const int* __restrict__ eids,
    const float* __restrict__ embed,
    const float* __restrict__ bufIn, float* __restrict__ bufOut)
{
    const int nitems = g_meta[LL * NNODE + layer];
    if ((int)blockIdx.x >= nitems) return;

    extern __shared__ float sm[];
    float* ws = sm;                    // 64 x 132
    float* xs = sm + 64 * XSTR;        // 32 x 132

    const int item = g_items[layer * ITEMS_MAX + blockIdx.x];
    const int node = item >> 6;
    const int c0   = item & 63;
    const int rh   = blockIdx.y;       // row half: rows [rh*64, rh*64+64)
    int kp = g_meta[layer * NNODE + node];
    kp = kp < LIST_CAP ? kp : LIST_CAP;
    const int nv = 2 * min(16, kp - c0);
    const int mmax = (nv + 7) >> 3;    // active vector groups (1..4)
    const int* lst = &g_list[(layer * NNODE + node) * LIST_CAP + c0];

    const int tid = threadIdx.x;
    const int lane = tid & 31, w = tid >> 5;   // 4 warps

    // ---- W stage: warp w loads ONLY rows [rh*64 + w*16, +16) via cp.async ----
    {
        uint32_t ws_u = (uint32_t)__cvta_generic_to_shared(ws);
        const float4* wsrc = (const float4*)(Wg + (size_t)node * (EE * EE));
        #pragma unroll
        for (int k = 0; k < 16; ++k) {
            int rl = w * 16 + k;                         // local row
            cpasync16(ws_u + (rl * XSTR + lane * 4) * 4,
                      wsrc + (size_t)(rh * 64 + rl) * 32 + lane);
        }
        asm volatile("cp.async.commit_group;");
    }

    // ---- xs gather: mmax*8 vectors x 128 floats, zero-pad beyond nv ----
    const int nf4 = mmax * 8 * 32;
    for (int f = tid; f < nf4; f += 128) {
        int v = f >> 5, i4 = f & 31;
        float4 val = make_float4(0.f, 0.f, 0.f, 0.f);
        if (v < nv) {
            int pr = lst[v >> 1];
            if (FIRST) {
                int id = (v & 1) ? eids[pr] : sids[pr];
                val = ((const float4*)embed)[(size_t)id * 32 + i4];
            } else {
                val = ((const float4*)bufIn)[((size_t)pr * 2 + (v & 1)) * 32 + i4];
            }
        }
        *(float4*)&xs[v * XSTR + i4 * 4] = val;
    }
    __syncthreads();                     // xs visible to all warps

    // ---- wait for OWN warp's W rows only, then compute ----
    asm volatile("cp.async.wait_group 0;");
    __syncwarp();

    const int rowlane = lane >> 3;       // 0..3
    const int vl = lane & 7;             // 0..7
    const float* bias_g = bias + node * EE + rh * 64;

    switch (mmax) {
        case 1: compute_tile<1>(ws, xs, lst, bufOut, bias_g, w, rowlane, vl, rh, nv); break;
        case 2: compute_tile<2>(ws, xs, lst, bufOut, bias_g, w, rowlane, vl, rh, nv); break;
        case 3: compute_tile<3>(ws, xs, lst, bufOut, bias_g, w, rowlane, vl, rh, nv); break;
        default: compute_tile<4>(ws, xs, lst, bufOut, bias_g, w, rowlane, vl, rh, nv); break;
    }
}

// ---------------- pooling: pooledT[f][b] ----------------
__global__ void pool_kernel(const float* __restrict__ buf,
                            const int* __restrict__ counts,
                            float* __restrict__ pooledT)
{
    const int b = blockIdx.x;
    const int f = threadIdx.x;          // 0..255
    const int half = f >> 7, fi = f & 127;
    float acc = 0.f, cs = 0.f;
    #pragma unroll
    for (int p = 0; p < PP; ++p) {
        float c = (float)counts[b * PP + p];
        acc += c * buf[((size_t)((b * PP + p) * 2 + half)) * EE + fi];
        cs += c;
    }
    pooledT[(size_t)f * BB + b] = acc / cs;
}

// ---------------- MLP layer (relu): yT[j][b] ----------------
template <int IN>
__global__ void mlp_kernel(const float* __restrict__ Wm, const float* __restrict__ bm,
                           const float* __restrict__ xT, float* __restrict__ yT)
{
    __shared__ float wt[IN * 8];
    const int jt = blockIdx.x * 8;
    const int t = threadIdx.x;          // batch index
    for (int f = t; f < IN * 8; f += 256) {
        int jj = f / IN, i = f % IN;
        wt[i * 8 + jj] = Wm[(size_t)(jt + jj) * IN + i];
    }
    __syncthreads();

    ull acc[4] = {0ull, 0ull, 0ull, 0ull};
    #pragma unroll 8
    for (int i = 0; i < IN; ++i) {
        ull pp = pack2(xT[(size_t)i * BB + t]);
        ulonglong2 wa = *(ulonglong2*)&wt[i * 8];
        ulonglong2 wb = *(ulonglong2*)&wt[i * 8 + 4];
        fma2(acc[0], wa.x, pp);
        fma2(acc[1], wa.y, pp);
        fma2(acc[2], wb.x, pp);
        fma2(acc[3], wb.y, pp);
    }
    #pragma unroll
    for (int q = 0; q < 4; ++q) {
        int j0 = jt + 2 * q, j1 = j0 + 1;
        float v0 = __uint_as_float((unsigned)acc[q]) + bm[j0];
        float v1 = __uint_as_float((unsigned)(acc[q] >> 32)) + bm[j1];
        yT[(size_t)j0 * BB + t] = fmaxf(v0, 0.f);
        yT[(size_t)j1 * BB + t] = fmaxf(v1, 0.f);
    }
}

// ---------------- final ----------------
__global__ void out_kernel(const float* __restrict__ W3, const float* __restrict__ b3,
                           const float* __restrict__ h2T, float* __restrict__ out)
{
    const int t = threadIdx.x;
    float acc = 0.f;
    #pragma unroll 8
    for (int j = 0; j < C2; ++j)
        acc += W3[j] * h2T[(size_t)j * BB + t];
    acc += b3[0];
    out[t] = 1.f / (1.f + expf(-acc));
}

// ---------------- launch ----------------
extern "C" void kernel_launch(void* const* d_in, const int* in_sizes, int n_in,
                              void* d_out, int out_size)
{
    const int*   sids   = (const int*)d_in[0];
    const int*   eids   = (const int*)d_in[1];
    const int*   mids   = (const int*)d_in[2];
    const int*   counts = (const int*)d_in[3];
    const float* embed  = (const float*)d_in[4];
    const float* W      = (const float*)d_in[5];
    const float* bnode  = (const float*)d_in[6];
    const float* W1     = (const float*)d_in[7];
    const float* b1     = (const float*)d_in[8];
    const float* W2     = (const float*)d_in[9];
    const float* b2     = (const float*)d_in[10];
    const float* W3     = (const float*)d_in[11];
    const float* b3     = (const float*)d_in[12];

    float *bufA, *bufB, *pooledT, *h1T, *h2T;
    int *meta;
    cudaGetSymbolAddress((void**)&bufA, g_bufA);
    cudaGetSymbolAddress((void**)&bufB, g_bufB);
    cudaGetSymbolAddress((void**)&pooledT, g_pooledT);
    cudaGetSymbolAddress((void**)&h1T, g_h1T);
    cudaGetSymbolAddress((void**)&h2T, g_h2T);
    cudaGetSymbolAddress((void**)&meta, g_meta);

    const int smem = SMEM_LAYER;   // 50688 bytes
    cudaFuncSetAttribute(layer_kernel<true>,  cudaFuncAttributeMaxDynamicSharedMemorySize, smem);
    cudaFuncSetAttribute(layer_kernel<false>, cudaFuncAttributeMaxDynamicSharedMemorySize, smem);

    // reset counters + build node->pair lists + work items for all 4 layers
    cudaMemsetAsync(meta, 0, (LL * NNODE + LL) * sizeof(int));
    build_lists_kernel<<<(NPAIR * LL + 255) / 256, 256>>>(mids);
    build_items_kernel<<<(LL * NNODE + 255) / 256, 256>>>();

    dim3 lgrid(ITEMS_MAX, 2);
    layer_kernel<true ><<<lgrid, 128, smem>>>(W, bnode, 0, sids, eids, embed, nullptr, bufA);
    layer_kernel<false><<<lgrid, 128, smem>>>(W, bnode, 1, sids, eids, embed, bufA, bufB);
    layer_kernel<false><<<lgrid, 128, smem>>>(W, bnode, 2, sids, eids, embed, bufB, bufA);
    layer_kernel<false><<<lgrid, 128, smem>>>(W, bnode, 3, sids, eids, embed, bufA, bufB);

    pool_kernel<<<BB, 256>>>(bufB, counts, pooledT);
    mlp_kernel<2 * EE><<<C1 / 8, 256>>>(W1, b1, pooledT, h1T);
    mlp_kernel<C1>    <<<C2 / 8, 256>>>(W2, b2, h1T, h2T);
    out_kernel<<<1, 256>>>(W3, b3, h2T, (float*)d_out);
}